// round 2
// baseline (speedup 1.0000x reference)
#include <cuda_runtime.h>
#include <cuda_bf16.h>
#include <stdint.h>

// Problem constants
#define BB   64
#define LMAX 4096
#define DD   128
#define RL   64
#define RD   16
#define DOUT 512
#define LN_EPS 1e-5f

#define CHUNK 256   // L-rows per stage-A block
#define TILE  32    // L-rows per inner tile

// -------- device scratch (no allocations allowed) --------
__device__ int   g_mode;            // 0=i32, 1=u8, 2=f32, 3=bf16
__device__ int   g_len[BB];
__device__ float g_U[BB * RL * RD];     // 64*1024
__device__ float g_z[BB * DOUT];
__device__ float g_h[BB * DOUT];
__device__ float g_ha[BB * DOUT];

// -------------------------------------------------------------------
// k0: detect mask dtype. mask[0][0] is always true (lengths >= 1).
//  f32  -> word0 == 0x3F800000
//  bf16 -> word0 == 0x3F803F80 (len0>=2) or 0x00003F80 (len0==1)
//  u8   -> some byte at index i%4 != 0 is nonzero (contiguous runs)
//  i32  -> otherwise
// -------------------------------------------------------------------
__global__ void k_detect(const unsigned char* __restrict__ mask_raw) {
    __shared__ int s_flag;
    const unsigned* mw = (const unsigned*)mask_raw;
    unsigned W0 = mw[0];
    int t = threadIdx.x;
    if (W0 == 0x3F800000u) { if (t == 0) g_mode = 2; return; }
    if (W0 == 0x3F803F80u || W0 == 0x00003F80u) { if (t == 0) g_mode = 3; return; }
    if (t == 0) s_flag = 0;
    __syncthreads();
    int local = 0;
    // scan first 262144 bytes (safe for both u8 and i32 storage)
    for (int i = t; i < (BB * LMAX) / 4; i += blockDim.x) {
        unsigned w = mw[i];
        if (w & 0xFFFFFF00u) local = 1;   // any nonzero byte at pos 1..3
    }
    if (local) atomicOr(&s_flag, 1);
    __syncthreads();
    if (t == 0) g_mode = s_flag ? 1 : 0;
}

// -------------------------------------------------------------------
// k1: blocks 0..63 compute per-row lengths (count of nonzero mask);
//     blocks 64..67 zero scratch buffers + d_out.
// -------------------------------------------------------------------
__global__ void k_prep(const unsigned char* __restrict__ mask_raw,
                       float* __restrict__ out) {
    int b = blockIdx.x;
    int t = threadIdx.x;
    if (b < BB) {
        int mode = g_mode;
        int base = b * LMAX;
        int cnt = 0;
        if (mode == 0) {
            const int* m = (const int*)mask_raw;
            for (int i = t; i < LMAX; i += 256) cnt += (m[base + i] != 0);
        } else if (mode == 1) {
            const unsigned char* m = mask_raw;
            for (int i = t; i < LMAX; i += 256) cnt += (m[base + i] != 0);
        } else if (mode == 2) {
            const float* m = (const float*)mask_raw;
            for (int i = t; i < LMAX; i += 256) cnt += (m[base + i] != 0.0f);
        } else {
            const unsigned short* m = (const unsigned short*)mask_raw;
            for (int i = t; i < LMAX; i += 256) cnt += (m[base + i] != 0);
        }
        // block reduce
        for (int o = 16; o > 0; o >>= 1) cnt += __shfl_down_sync(0xFFFFFFFFu, cnt, o);
        __shared__ int sred[8];
        if ((t & 31) == 0) sred[t >> 5] = cnt;
        __syncthreads();
        if (t == 0) {
            int tot = 0;
            #pragma unroll
            for (int i = 0; i < 8; ++i) tot += sred[i];
            g_len[b] = tot;
        }
    } else {
        // zero: g_U (65536) | g_z (32768) | g_h (32768) | out (32768)
        int zb = b - BB;                      // 0..3
        int tot = BB * RL * RD + 3 * BB * DOUT;   // 163840
        for (int i = zb * 256 + t; i < tot; i += 4 * 256) {
            if (i < 65536)            g_U[i] = 0.0f;
            else if (i < 65536 + 32768) g_z[i - 65536] = 0.0f;
            else if (i < 65536 + 65536) g_h[i - 65536 - 32768] = 0.0f;
            else                       out[i - 65536 - 65536] = 0.0f;
        }
    }
}

// -------------------------------------------------------------------
// k2 (heavy): per (b, L-chunk) block:
//   Y[l][r] = sum_d emb[b,l,d] * B_c[d,r]    (only l < len[b])
//   U[b,k,r] += sum_l Y[l][r] * A_c[l,k]
// Block: 256 threads.
//   GEMM1 mapping: row = t>>3 (32 rows), rp = t&7 (2 r's each)
//   GEMM2 mapping: k = t>>2 (64), rb = (t&3)*4 (4 r's each), regs persist
// -------------------------------------------------------------------
__global__ __launch_bounds__(256) void k_stageA(
        const float* __restrict__ emb,
        const float* __restrict__ Bc,
        const float* __restrict__ Ac) {
    int b     = blockIdx.x & (BB - 1);
    int chunk = blockIdx.x >> 6;
    int len   = g_len[b];
    int l0    = chunk * CHUNK;
    if (l0 >= len) return;
    int nrows = min(CHUNK, len - l0);

    __shared__ __align__(16) float Bs[DD * RD];        // 8 KB
    __shared__ __align__(16) float Xs[TILE * 132];     // padded, ~16.5 KB
    __shared__ __align__(16) float As[TILE * RL];      // 8 KB
    __shared__ __align__(16) float Ys[TILE * RD];      // 2 KB

    int t = threadIdx.x;
    for (int i = t; i < DD * RD; i += 256) Bs[i] = Bc[i];

    int k_own = t >> 2;
    int rb    = (t & 3) * 4;
    float acc0 = 0.f, acc1 = 0.f, acc2 = 0.f, acc3 = 0.f;

    int row1 = t >> 3;
    int rp   = t & 7;

    const float* embB = emb + (size_t)b * LMAX * DD;

    int ntiles = (nrows + TILE - 1) >> 5;
    for (int tile = 0; tile < ntiles; ++tile) {
        int lt    = l0 + tile * TILE;
        int valid = min(TILE, nrows - tile * TILE);

        __syncthreads();  // protect smem reused from previous iteration
        // load X tile (zero invalid rows), 1024 float4 slots
        for (int i = t; i < TILE * 32; i += 256) {
            int row = i >> 5, seg = i & 31;
            float4 v = make_float4(0.f, 0.f, 0.f, 0.f);
            if (row < valid)
                v = *(const float4*)(embB + (size_t)(lt + row) * DD + seg * 4);
            *(float4*)(Xs + row * 132 + seg * 4) = v;
        }
        // load A tile
        for (int i = t; i < TILE * RL; i += 256)
            As[i] = Ac[(size_t)(lt + (i >> 6)) * RL + (i & 63)];
        __syncthreads();

        // GEMM1: Y[row][2rp..2rp+1]
        float a0 = 0.f, a1 = 0.f;
        const float* xr = Xs + row1 * 132;
        const float* bp = Bs + rp * 2;
        #pragma unroll 8
        for (int s = 0; s < 32; ++s) {
            float4 x4 = *(const float4*)(xr + s * 4);
            float2 c0 = *(const float2*)(bp + (4 * s + 0) * RD);
            float2 c1 = *(const float2*)(bp + (4 * s + 1) * RD);
            float2 c2 = *(const float2*)(bp + (4 * s + 2) * RD);
            float2 c3 = *(const float2*)(bp + (4 * s + 3) * RD);
            a0 = fmaf(x4.x, c0.x, a0); a1 = fmaf(x4.x, c0.y, a1);
            a0 = fmaf(x4.y, c1.x, a0); a1 = fmaf(x4.y, c1.y, a1);
            a0 = fmaf(x4.z, c2.x, a0); a1 = fmaf(x4.z, c2.y, a1);
            a0 = fmaf(x4.w, c3.x, a0); a1 = fmaf(x4.w, c3.y, a1);
        }
        *(float2*)(Ys + row1 * RD + rp * 2) = make_float2(a0, a1);
        __syncthreads();

        // GEMM2: U[k][rb..rb+3] += A[l][k] * Y[l][rb..rb+3]
        #pragma unroll 8
        for (int row = 0; row < TILE; ++row) {
            float a  = As[row * RL + k_own];
            float4 y = *(const float4*)(Ys + row * RD + rb);
            acc0 = fmaf(a, y.x, acc0);
            acc1 = fmaf(a, y.y, acc1);
            acc2 = fmaf(a, y.z, acc2);
            acc3 = fmaf(a, y.w, acc3);
        }
    }

    float* Ub = g_U + b * (RL * RD) + k_own * RD + rb;
    atomicAdd(Ub + 0, acc0);
    atomicAdd(Ub + 1, acc1);
    atomicAdd(Ub + 2, acc2);
    atomicAdd(Ub + 3, acc3);
}

// -------------------------------------------------------------------
// k3: z = U_flat[64x1024] @ H_c[1024x512], split-K with atomics.
// grid 128: nt = bid&15 (32 cols), ks = bid>>4 (8 k-slices of 128)
// -------------------------------------------------------------------
__global__ __launch_bounds__(256) void k_zgemm(const float* __restrict__ Hc) {
    __shared__ float Us[BB * 130];
    int nt = blockIdx.x & 15, ks = blockIdx.x >> 4;
    int t = threadIdx.x;
    for (int i = t; i < BB * 128; i += 256) {
        int bb = i >> 7, kk = i & 127;
        Us[bb * 130 + kk] = g_U[bb * 1024 + ks * 128 + kk];
    }
    __syncthreads();
    int b  = t >> 2;
    int n0 = nt * 32 + (t & 3) * 8;
    float acc[8] = {0.f, 0.f, 0.f, 0.f, 0.f, 0.f, 0.f, 0.f};
    const float* H = Hc + (size_t)(ks * 128) * DOUT + n0;
    const float* us = Us + b * 130;
    #pragma unroll 4
    for (int kk = 0; kk < 128; ++kk) {
        float u = us[kk];
        float4 h0 = *(const float4*)(H + (size_t)kk * DOUT);
        float4 h1 = *(const float4*)(H + (size_t)kk * DOUT + 4);
        acc[0] = fmaf(u, h0.x, acc[0]); acc[1] = fmaf(u, h0.y, acc[1]);
        acc[2] = fmaf(u, h0.z, acc[2]); acc[3] = fmaf(u, h0.w, acc[3]);
        acc[4] = fmaf(u, h1.x, acc[4]); acc[5] = fmaf(u, h1.y, acc[5]);
        acc[6] = fmaf(u, h1.z, acc[6]); acc[7] = fmaf(u, h1.w, acc[7]);
    }
    float* zp = g_z + b * DOUT + n0;
    #pragma unroll
    for (int j = 0; j < 8; ++j) atomicAdd(zp + j, acc[j]);
}

// -------------------------------------------------------------------
// k4: h_pre = z[64x512] @ W1[512x512], split-K (4 slices of 128).
// grid 64: nt = bid&15, ks = bid>>4
// -------------------------------------------------------------------
__global__ __launch_bounds__(256) void k_hgemm(const float* __restrict__ W1) {
    __shared__ float zs[BB * 130];
    int nt = blockIdx.x & 15, ks = blockIdx.x >> 4;
    int t = threadIdx.x;
    for (int i = t; i < BB * 128; i += 256) {
        int bb = i >> 7, kk = i & 127;
        zs[bb * 130 + kk] = g_z[bb * DOUT + ks * 128 + kk];
    }
    __syncthreads();
    int b  = t >> 2;
    int n0 = nt * 32 + (t & 3) * 8;
    float acc[8] = {0.f, 0.f, 0.f, 0.f, 0.f, 0.f, 0.f, 0.f};
    const float* W = W1 + (size_t)(ks * 128) * DOUT + n0;
    const float* us = zs + b * 130;
    #pragma unroll 4
    for (int kk = 0; kk < 128; ++kk) {
        float u = us[kk];
        float4 h0 = *(const float4*)(W + (size_t)kk * DOUT);
        float4 h1 = *(const float4*)(W + (size_t)kk * DOUT + 4);
        acc[0] = fmaf(u, h0.x, acc[0]); acc[1] = fmaf(u, h0.y, acc[1]);
        acc[2] = fmaf(u, h0.z, acc[2]); acc[3] = fmaf(u, h0.w, acc[3]);
        acc[4] = fmaf(u, h1.x, acc[4]); acc[5] = fmaf(u, h1.y, acc[5]);
        acc[6] = fmaf(u, h1.z, acc[6]); acc[7] = fmaf(u, h1.w, acc[7]);
    }
    float* hp = g_h + b * DOUT + n0;
    #pragma unroll
    for (int j = 0; j < 8; ++j) atomicAdd(hp + j, acc[j]);
}

// -------------------------------------------------------------------
// k5: per-row bias + LayerNorm + ReLU. grid 64, 256 threads (2 elems each)
// -------------------------------------------------------------------
__global__ __launch_bounds__(256) void k_ln(const float* __restrict__ b1,
                                            const float* __restrict__ lnw,
                                            const float* __restrict__ lnb) {
    int b = blockIdx.x, t = threadIdx.x;
    float v0 = g_h[b * DOUT + t]       + b1[t];
    float v1 = g_h[b * DOUT + 256 + t] + b1[256 + t];
    float s  = v0 + v1;
    float sq = v0 * v0 + v1 * v1;
    for (int o = 16; o > 0; o >>= 1) {
        s  += __shfl_down_sync(0xFFFFFFFFu, s,  o);
        sq += __shfl_down_sync(0xFFFFFFFFu, sq, o);
    }
    __shared__ float rs[8], rq[8];
    if ((t & 31) == 0) { rs[t >> 5] = s; rq[t >> 5] = sq; }
    __syncthreads();
    float tot = 0.f, totq = 0.f;
    #pragma unroll
    for (int i = 0; i < 8; ++i) { tot += rs[i]; totq += rq[i]; }
    float mu  = tot / (float)DOUT;
    float var = fmaxf(totq / (float)DOUT - mu * mu, 0.f);
    float rstd = rsqrtf(var + LN_EPS);
    float o0 = (v0 - mu) * rstd * lnw[t]       + lnb[t];
    float o1 = (v1 - mu) * rstd * lnw[256 + t] + lnb[256 + t];
    g_ha[b * DOUT + t]       = fmaxf(o0, 0.f);
    g_ha[b * DOUT + 256 + t] = fmaxf(o1, 0.f);
}

// -------------------------------------------------------------------
// k6: out = h_act @ W2 + b2, split-K (4 slices); b2 added by ks==0.
// -------------------------------------------------------------------
__global__ __launch_bounds__(256) void k_outgemm(const float* __restrict__ W2,
                                                 const float* __restrict__ b2,
                                                 float* __restrict__ out) {
    __shared__ float zs[BB * 130];
    int nt = blockIdx.x & 15, ks = blockIdx.x >> 4;
    int t = threadIdx.x;
    for (int i = t; i < BB * 128; i += 256) {
        int bb = i >> 7, kk = i & 127;
        zs[bb * 130 + kk] = g_ha[bb * DOUT + ks * 128 + kk];
    }
    __syncthreads();
    int b  = t >> 2;
    int n0 = nt * 32 + (t & 3) * 8;
    float acc[8] = {0.f, 0.f, 0.f, 0.f, 0.f, 0.f, 0.f, 0.f};
    const float* W = W2 + (size_t)(ks * 128) * DOUT + n0;
    const float* us = zs + b * 130;
    #pragma unroll 4
    for (int kk = 0; kk < 128; ++kk) {
        float u = us[kk];
        float4 h0 = *(const float4*)(W + (size_t)kk * DOUT);
        float4 h1 = *(const float4*)(W + (size_t)kk * DOUT + 4);
        acc[0] = fmaf(u, h0.x, acc[0]); acc[1] = fmaf(u, h0.y, acc[1]);
        acc[2] = fmaf(u, h0.z, acc[2]); acc[3] = fmaf(u, h0.w, acc[3]);
        acc[4] = fmaf(u, h1.x, acc[4]); acc[5] = fmaf(u, h1.y, acc[5]);
        acc[6] = fmaf(u, h1.z, acc[6]); acc[7] = fmaf(u, h1.w, acc[7]);
    }
    if (ks == 0) {
        #pragma unroll
        for (int j = 0; j < 8; ++j) acc[j] += b2[n0 + j];
    }
    float* op = out + b * DOUT + n0;
    #pragma unroll
    for (int j = 0; j < 8; ++j) atomicAdd(op + j, acc[j]);
}

// -------------------------------------------------------------------
extern "C" void kernel_launch(void* const* d_in, const int* in_sizes, int n_in,
                              void* d_out, int out_size) {
    const float*         emb  = (const float*)d_in[0];
    const unsigned char* mask = (const unsigned char*)d_in[1];
    const float*         Bc   = (const float*)d_in[2];
    const float*         Ac   = (const float*)d_in[3];
    const float*         Hc   = (const float*)d_in[4];
    const float*         W1   = (const float*)d_in[5];
    const float*         b1   = (const float*)d_in[6];
    const float*         lnw  = (const float*)d_in[7];
    const float*         lnb  = (const float*)d_in[8];
    const float*         W2   = (const float*)d_in[9];
    const float*         b2   = (const float*)d_in[10];
    float* out = (float*)d_out;

    k_detect<<<1, 256>>>(mask);
    k_prep<<<68, 256>>>(mask, out);
    k_stageA<<<BB * (LMAX / CHUNK), 256>>>(emb, Bc, Ac);   // 1024 blocks
    k_zgemm<<<128, 256>>>(Hc);
    k_hgemm<<<64, 256>>>(W1);
    k_ln<<<BB, 256>>>(b1, lnw, lnb);
    k_outgemm<<<64, 256>>>(W2, b2, out);
}

// round 4
// speedup vs baseline: 2.0170x; 2.0170x over previous
#include <cuda_runtime.h>
#include <cuda_bf16.h>
#include <stdint.h>

// Problem constants
#define BB   64
#define LMAX 4096
#define DD   128
#define RL   64
#define RD   16
#define DOUT 512
#define LN_EPS 1e-5f

#define CHUNK 512   // L-rows per stage-A block
#define TILE  32    // L-rows per inner tile

// -------- device scratch (no allocations allowed) --------
__device__ int   g_mode;            // 0=i32, 1=u8, 2=f32, 3=bf16
__device__ int   g_len[BB];
__device__ float g_U[BB * RL * RD];     // 64*1024
__device__ float g_z[BB * DOUT];
__device__ float g_h[BB * DOUT];
__device__ float g_ha[BB * DOUT];

// ---------------- cp.async helpers ----------------
__device__ __forceinline__ void cp_async16(float* smem_dst, const float* gsrc, int src_bytes) {
    unsigned sa = (unsigned)__cvta_generic_to_shared(smem_dst);
    asm volatile("cp.async.cg.shared.global [%0], [%1], 16, %2;\n"
                 :: "r"(sa), "l"(gsrc), "r"(src_bytes));
}
__device__ __forceinline__ void cp_commit() {
    asm volatile("cp.async.commit_group;\n");
}
template<int N> __device__ __forceinline__ void cp_wait() {
    asm volatile("cp.async.wait_group %0;\n" :: "n"(N));
}

// -------------------------------------------------------------------
// k0: detect mask dtype. mask[0][0] is always true (lengths >= 1).
// -------------------------------------------------------------------
__global__ void k_detect(const unsigned char* __restrict__ mask_raw) {
    __shared__ int s_flag;
    const unsigned* mw = (const unsigned*)mask_raw;
    unsigned W0 = mw[0];
    int t = threadIdx.x;
    if (W0 == 0x3F800000u) { if (t == 0) g_mode = 2; return; }
    if (W0 == 0x3F803F80u || W0 == 0x00003F80u) { if (t == 0) g_mode = 3; return; }
    if (t == 0) s_flag = 0;
    __syncthreads();
    int local = 0;
    #pragma unroll 4
    for (int i = t; i < 16384; i += 512) {     // first 64 KB only (always in-bounds)
        unsigned w = mw[i];
        if (w & 0xFFFFFF00u) local = 1;
    }
    if (local) atomicOr(&s_flag, 1);
    __syncthreads();
    if (t == 0) g_mode = s_flag ? 1 : 0;
}

// -------------------------------------------------------------------
// k1: blocks 0..63 compute per-row lengths; blocks 64..67 zero scratch + out.
// -------------------------------------------------------------------
__global__ void k_prep(const unsigned char* __restrict__ mask_raw,
                       float* __restrict__ out) {
    int b = blockIdx.x;
    int t = threadIdx.x;
    if (b < BB) {
        int mode = g_mode;
        int base = b * LMAX;
        int cnt = 0;
        if (mode == 0) {
            const int* m = (const int*)mask_raw;
            for (int i = t; i < LMAX; i += 256) cnt += (m[base + i] != 0);
        } else if (mode == 1) {
            const unsigned char* m = mask_raw;
            for (int i = t; i < LMAX; i += 256) cnt += (m[base + i] != 0);
        } else if (mode == 2) {
            const float* m = (const float*)mask_raw;
            for (int i = t; i < LMAX; i += 256) cnt += (m[base + i] != 0.0f);
        } else {
            const unsigned short* m = (const unsigned short*)mask_raw;
            for (int i = t; i < LMAX; i += 256) cnt += (m[base + i] != 0);
        }
        for (int o = 16; o > 0; o >>= 1) cnt += __shfl_down_sync(0xFFFFFFFFu, cnt, o);
        __shared__ int sred[8];
        if ((t & 31) == 0) sred[t >> 5] = cnt;
        __syncthreads();
        if (t == 0) {
            int tot = 0;
            #pragma unroll
            for (int i = 0; i < 8; ++i) tot += sred[i];
            g_len[b] = tot;
        }
    } else {
        int zb = b - BB;                          // 0..3
        int tot = BB * RL * RD + 3 * BB * DOUT;   // 163840
        for (int i = zb * 256 + t; i < tot; i += 4 * 256) {
            if (i < 65536)              g_U[i] = 0.0f;
            else if (i < 65536 + 32768) g_z[i - 65536] = 0.0f;
            else if (i < 65536 + 65536) g_h[i - 65536 - 32768] = 0.0f;
            else                        out[i - 65536 - 65536] = 0.0f;
        }
    }
}

// -------------------------------------------------------------------
// k2 (heavy): per (b, 512-row chunk) block, double-buffered via cp.async.
// -------------------------------------------------------------------
__device__ __forceinline__ void issue_tile(const float* embB, const float* Ac,
        float* Xbuf, float* Abuf, int lt, int valid, int t) {
    #pragma unroll
    for (int j = 0; j < 4; ++j) {
        int i = t + j * 256;              // 0..1023
        int row = i >> 5, seg = i & 31;
        const float* src = embB + (size_t)(lt + row) * DD + seg * 4;
        int bytes = (row < valid) ? 16 : 0;
        cp_async16(Xbuf + row * 132 + seg * 4, src, bytes);
    }
    #pragma unroll
    for (int j = 0; j < 2; ++j) {
        int i = t + j * 256;              // 0..511
        int row = i >> 4, seg = i & 15;
        cp_async16(Abuf + row * RL + seg * 4,
                   Ac + (size_t)(lt + row) * RL + seg * 4, 16);
    }
}

__global__ __launch_bounds__(256) void k_stageA(
        const float* __restrict__ emb,
        const float* __restrict__ Bc,
        const float* __restrict__ Ac) {
    extern __shared__ float sm[];
    float* Bs  = sm;            // 2048
    float* Ys  = sm + 2048;     // 512
    float* Xs0 = sm + 2560;     // 4224
    float* Xs1 = sm + 6784;     // 4224
    float* As0 = sm + 11008;    // 2048
    float* As1 = sm + 13056;    // 2048  (total 15104 floats = 60416 B)

    int b     = blockIdx.x & (BB - 1);
    int chunk = blockIdx.x >> 6;
    int len   = g_len[b];
    int l0    = chunk * CHUNK;
    if (l0 >= len) return;
    int nrows = min(CHUNK, len - l0);

    int t = threadIdx.x;
    for (int i = t; i < DD * RD; i += 256) Bs[i] = Bc[i];

    const float* embB = emb + (size_t)b * LMAX * DD;
    int ntiles = (nrows + TILE - 1) >> 5;

    int k_own = t >> 2;
    int rb    = (t & 3) * 4;
    float acc0 = 0.f, acc1 = 0.f, acc2 = 0.f, acc3 = 0.f;
    int row1 = t >> 3;
    int rp   = t & 7;

    issue_tile(embB, Ac, Xs0, As0, l0, min(TILE, nrows), t);
    cp_commit();

    for (int tile = 0; tile < ntiles; ++tile) {
        float* Xb = (tile & 1) ? Xs1 : Xs0;
        float* Ab = (tile & 1) ? As1 : As0;
        if (tile + 1 < ntiles) {
            int lt    = l0 + (tile + 1) * TILE;
            int valid = min(TILE, nrows - (tile + 1) * TILE);
            issue_tile(embB, Ac, (tile & 1) ? Xs0 : Xs1,
                       (tile & 1) ? As0 : As1, lt, valid, t);
            cp_commit();
            cp_wait<1>();
        } else {
            cp_wait<0>();
        }
        __syncthreads();

        // GEMM1: Y[row][2rp..2rp+1]
        {
            float a0 = 0.f, a1 = 0.f;
            const float* xr = Xb + row1 * 132;
            const float* bp = Bs + rp * 2;
            #pragma unroll 8
            for (int s = 0; s < 32; ++s) {
                float4 x4 = *(const float4*)(xr + s * 4);
                float2 c0 = *(const float2*)(bp + (4 * s + 0) * RD);
                float2 c1 = *(const float2*)(bp + (4 * s + 1) * RD);
                float2 c2 = *(const float2*)(bp + (4 * s + 2) * RD);
                float2 c3 = *(const float2*)(bp + (4 * s + 3) * RD);
                a0 = fmaf(x4.x, c0.x, a0); a1 = fmaf(x4.x, c0.y, a1);
                a0 = fmaf(x4.y, c1.x, a0); a1 = fmaf(x4.y, c1.y, a1);
                a0 = fmaf(x4.z, c2.x, a0); a1 = fmaf(x4.z, c2.y, a1);
                a0 = fmaf(x4.w, c3.x, a0); a1 = fmaf(x4.w, c3.y, a1);
            }
            *(float2*)(Ys + row1 * RD + rp * 2) = make_float2(a0, a1);
        }
        __syncthreads();

        // GEMM2: U[k][rb..rb+3] += A[l][k] * Y[l][rb..rb+3]
        #pragma unroll 8
        for (int row = 0; row < TILE; ++row) {
            float a  = Ab[row * RL + k_own];
            float4 y = *(const float4*)(Ys + row * RD + rb);
            acc0 = fmaf(a, y.x, acc0);
            acc1 = fmaf(a, y.y, acc1);
            acc2 = fmaf(a, y.z, acc2);
            acc3 = fmaf(a, y.w, acc3);
        }
        __syncthreads();
    }

    float* Ub = g_U + b * (RL * RD) + k_own * RD + rb;
    atomicAdd(Ub + 0, acc0);
    atomicAdd(Ub + 1, acc1);
    atomicAdd(Ub + 2, acc2);
    atomicAdd(Ub + 3, acc3);
}

// -------------------------------------------------------------------
// Tail GEMM: C[64 x 512] += A[64 x Ktot] @ W[Ktot x 512] (+bias on ks==0)
// MODE selects device-global src/dst IN DEVICE CODE (the R3 bug was passing
// __device__ globals as host-side kernel args -> garbage pointers).
//   MODE 0: A=g_U  (Ktot=1024), C=g_z
//   MODE 1: A=g_z  (Ktot=512),  C=g_h
//   MODE 2: A=g_ha (Ktot=512),  C=outp (real d_out arg), bias=b2
// -------------------------------------------------------------------
template<int KC, int MODE>
__global__ __launch_bounds__(256) void k_tgemm(
        const float* __restrict__ W, float* __restrict__ outp,
        const float* __restrict__ bias, int Ktot) {
    const float* A = (MODE == 0) ? g_U : (MODE == 1) ? g_z : g_ha;
    float*       C = (MODE == 0) ? g_z : (MODE == 1) ? g_h : outp;

    constexpr int SA = KC + 1;
    __shared__ float As[BB * SA];   // KC=64: 16.6 KB
    __shared__ float Ws[KC * 32];   // 8 KB

    int nt = blockIdx.x & 15;
    int ks = blockIdx.x >> 4;
    int n0 = nt * 32;
    int kbase = ks * KC;
    int t = threadIdx.x;

    #pragma unroll 4
    for (int i = t; i < BB * KC; i += 256) {
        int row = i / KC, k = i % KC;
        As[row * SA + k] = A[(size_t)row * Ktot + kbase + k];
    }
    #pragma unroll 2
    for (int i = t; i < KC * 8; i += 256) {
        int row = i >> 3, seg = i & 7;
        *(float4*)&Ws[row * 32 + seg * 4] =
            *(const float4*)&W[(size_t)(kbase + row) * DOUT + n0 + seg * 4];
    }
    __syncthreads();

    int l  = t & 31;
    int wn = t >> 5;          // 0..7
    float c00 = 0.f, c01 = 0.f, c02 = 0.f, c03 = 0.f;
    float c10 = 0.f, c11 = 0.f, c12 = 0.f, c13 = 0.f;
    const float* a0p = As + l * SA;
    const float* a1p = As + (l + 32) * SA;
    const float* wp  = Ws + wn * 4;
    #pragma unroll 8
    for (int k = 0; k < KC; ++k) {
        float a0 = a0p[k];
        float a1 = a1p[k];
        float4 w = *(const float4*)(wp + k * 32);
        c00 = fmaf(a0, w.x, c00); c01 = fmaf(a0, w.y, c01);
        c02 = fmaf(a0, w.z, c02); c03 = fmaf(a0, w.w, c03);
        c10 = fmaf(a1, w.x, c10); c11 = fmaf(a1, w.y, c11);
        c12 = fmaf(a1, w.z, c12); c13 = fmaf(a1, w.w, c13);
    }
    int col = n0 + wn * 4;
    if (MODE == 2 && ks == 0) {
        float4 bv = *(const float4*)(bias + col);
        c00 += bv.x; c01 += bv.y; c02 += bv.z; c03 += bv.w;
        c10 += bv.x; c11 += bv.y; c12 += bv.z; c13 += bv.w;
    }
    float* Cp0 = C + (size_t)l * DOUT + col;
    float* Cp1 = C + (size_t)(l + 32) * DOUT + col;
    atomicAdd(Cp0 + 0, c00); atomicAdd(Cp0 + 1, c01);
    atomicAdd(Cp0 + 2, c02); atomicAdd(Cp0 + 3, c03);
    atomicAdd(Cp1 + 0, c10); atomicAdd(Cp1 + 1, c11);
    atomicAdd(Cp1 + 2, c12); atomicAdd(Cp1 + 3, c13);
}

// -------------------------------------------------------------------
// k5: per-row bias + LayerNorm + ReLU. grid 64, 256 threads (2 elems each)
// -------------------------------------------------------------------
__global__ __launch_bounds__(256) void k_ln(const float* __restrict__ b1,
                                            const float* __restrict__ lnw,
                                            const float* __restrict__ lnb) {
    int b = blockIdx.x, t = threadIdx.x;
    float v0 = g_h[b * DOUT + t]       + b1[t];
    float v1 = g_h[b * DOUT + 256 + t] + b1[256 + t];
    float s  = v0 + v1;
    float sq = v0 * v0 + v1 * v1;
    for (int o = 16; o > 0; o >>= 1) {
        s  += __shfl_down_sync(0xFFFFFFFFu, s,  o);
        sq += __shfl_down_sync(0xFFFFFFFFu, sq, o);
    }
    __shared__ float rs[8], rq[8];
    if ((t & 31) == 0) { rs[t >> 5] = s; rq[t >> 5] = sq; }
    __syncthreads();
    float tot = 0.f, totq = 0.f;
    #pragma unroll
    for (int i = 0; i < 8; ++i) { tot += rs[i]; totq += rq[i]; }
    float mu  = tot / (float)DOUT;
    float var = fmaxf(totq / (float)DOUT - mu * mu, 0.f);
    float rstd = rsqrtf(var + LN_EPS);
    float o0 = (v0 - mu) * rstd * lnw[t]       + lnb[t];
    float o1 = (v1 - mu) * rstd * lnw[256 + t] + lnb[256 + t];
    g_ha[b * DOUT + t]       = fmaxf(o0, 0.f);
    g_ha[b * DOUT + 256 + t] = fmaxf(o1, 0.f);
}

// -------------------------------------------------------------------
extern "C" void kernel_launch(void* const* d_in, const int* in_sizes, int n_in,
                              void* d_out, int out_size) {
    const float*         emb  = (const float*)d_in[0];
    const unsigned char* mask = (const unsigned char*)d_in[1];
    const float*         Bc   = (const float*)d_in[2];
    const float*         Ac   = (const float*)d_in[3];
    const float*         Hc   = (const float*)d_in[4];
    const float*         W1   = (const float*)d_in[5];
    const float*         b1   = (const float*)d_in[6];
    const float*         lnw  = (const float*)d_in[7];
    const float*         lnb  = (const float*)d_in[8];
    const float*         W2   = (const float*)d_in[9];
    const float*         b2   = (const float*)d_in[10];
    float* out = (float*)d_out;

    cudaFuncSetAttribute(k_stageA, cudaFuncAttributeMaxDynamicSharedMemorySize, 61440);

    k_detect<<<1, 512>>>(mask);
    k_prep<<<68, 256>>>(mask, out);
    k_stageA<<<BB * (LMAX / CHUNK), 256, 60416>>>(emb, Bc, Ac);   // 512 blocks
    // z = U @ Hc   (K=1024, 16 K-splits -> 256 blocks)
    k_tgemm<64, 0><<<256, 256>>>(Hc, nullptr, nullptr, 1024);
    // h = z @ W1   (K=512, 8 K-splits -> 128 blocks)
    k_tgemm<64, 1><<<128, 256>>>(W1, nullptr, nullptr, 512);
    k_ln<<<BB, 256>>>(b1, lnw, lnb);
    // out = ha @ W2 + b2
    k_tgemm<64, 2><<<128, 256>>>(W2, out, b2, 512);
}

// round 5
// speedup vs baseline: 3.1833x; 1.5783x over previous
#include <cuda_runtime.h>
#include <cuda_bf16.h>
#include <stdint.h>

// Problem constants
#define BB   64
#define LMAX 4096
#define DD   128
#define RL   64
#define RD   16
#define DOUT 512
#define LN_EPS 1e-5f

#define CHUNK 512   // L-rows per stage-A block
#define TILE  64    // L-rows per inner tile

// -------- device scratch (no allocations allowed) --------
__device__ int   g_mode;            // 0=i32, 1=u8, 2=f32, 3=bf16
__device__ int   g_len[BB];
__device__ float g_U[BB * RL * RD];     // 64*1024
__device__ float g_z[BB * DOUT];
__device__ float g_h[BB * DOUT];
__device__ float g_ha[BB * DOUT];

// ---------------- cp.async helpers ----------------
__device__ __forceinline__ void cp_async16(float* smem_dst, const float* gsrc, int src_bytes) {
    unsigned sa = (unsigned)__cvta_generic_to_shared(smem_dst);
    asm volatile("cp.async.cg.shared.global [%0], [%1], 16, %2;\n"
                 :: "r"(sa), "l"(gsrc), "r"(src_bytes));
}
__device__ __forceinline__ void cp_commit() {
    asm volatile("cp.async.commit_group;\n");
}
template<int N> __device__ __forceinline__ void cp_wait() {
    asm volatile("cp.async.wait_group %0;\n" :: "n"(N));
}

// -------------------------------------------------------------------
// k0: detect mask dtype. mask[0][0] is always true (lengths >= 1).
// -------------------------------------------------------------------
__global__ void k_detect(const unsigned char* __restrict__ mask_raw) {
    __shared__ int s_flag;
    const unsigned* mw = (const unsigned*)mask_raw;
    unsigned W0 = mw[0];
    int t = threadIdx.x;
    if (W0 == 0x3F800000u) { if (t == 0) g_mode = 2; return; }
    if (W0 == 0x3F803F80u || W0 == 0x00003F80u) { if (t == 0) g_mode = 3; return; }
    if (t == 0) s_flag = 0;
    __syncthreads();
    int local = 0;
    #pragma unroll 4
    for (int i = t; i < 16384; i += 512) {     // first 64 KB only (always in-bounds)
        unsigned w = mw[i];
        if (w & 0xFFFFFF00u) local = 1;
    }
    if (local) atomicOr(&s_flag, 1);
    __syncthreads();
    if (t == 0) g_mode = s_flag ? 1 : 0;
}

// -------------------------------------------------------------------
// k1: blocks 0..63 per-row lengths; blocks 64..67 zero scratch + out.
// -------------------------------------------------------------------
__global__ void k_prep(const unsigned char* __restrict__ mask_raw,
                       float* __restrict__ out) {
    int b = blockIdx.x;
    int t = threadIdx.x;
    if (b < BB) {
        int mode = g_mode;
        int base = b * LMAX;
        int cnt = 0;
        if (mode == 0) {
            const int* m = (const int*)mask_raw;
            for (int i = t; i < LMAX; i += 256) cnt += (m[base + i] != 0);
        } else if (mode == 1) {
            const unsigned char* m = mask_raw;
            for (int i = t; i < LMAX; i += 256) cnt += (m[base + i] != 0);
        } else if (mode == 2) {
            const float* m = (const float*)mask_raw;
            for (int i = t; i < LMAX; i += 256) cnt += (m[base + i] != 0.0f);
        } else {
            const unsigned short* m = (const unsigned short*)mask_raw;
            for (int i = t; i < LMAX; i += 256) cnt += (m[base + i] != 0);
        }
        for (int o = 16; o > 0; o >>= 1) cnt += __shfl_down_sync(0xFFFFFFFFu, cnt, o);
        __shared__ int sred[8];
        if ((t & 31) == 0) sred[t >> 5] = cnt;
        __syncthreads();
        if (t == 0) {
            int tot = 0;
            #pragma unroll
            for (int i = 0; i < 8; ++i) tot += sred[i];
            g_len[b] = tot;
        }
    } else {
        int zb = b - BB;                          // 0..3
        int tot = BB * RL * RD + 3 * BB * DOUT;   // 163840
        for (int i = zb * 256 + t; i < tot; i += 4 * 256) {
            if (i < 65536)              g_U[i] = 0.0f;
            else if (i < 65536 + 32768) g_z[i - 65536] = 0.0f;
            else if (i < 65536 + 65536) g_h[i - 65536 - 32768] = 0.0f;
            else                        out[i - 65536 - 65536] = 0.0f;
        }
    }
}

// -------------------------------------------------------------------
// k2 (heavy): per (b, 512-row chunk), TILE=64 rows per inner tile.
// smem (floats): Bs[2048] | Ys[64*20] | Xs[64*132] | As0[4096] | As1[4096]
//   = 19968 floats = 79872 B dynamic.
// GEMM1: warp w: colgrp c=w&3 (4 cols, B reads warp-uniform broadcast),
//        row = (w>>2)*32 + lane (X reads conflict-free, stride 132).
// GEMM2: k = t&63 (lane-consecutive A reads), rgrp = t>>6 (warp-uniform
//        Ys float4 broadcast). U accumulators persist in regs.
// Pipeline: X single-buffered (refilled during GEMM2), A double-buffered.
// -------------------------------------------------------------------
__device__ __forceinline__ void issue_tile64(const float* embB, const float* Ac,
        float* Xbuf, float* Abuf, int lt, int valid, int t) {
    #pragma unroll
    for (int j = 0; j < 8; ++j) {             // 2048 X float4-chunks
        int i = t + j * 256;
        int row = i >> 5, seg = i & 31;
        cp_async16(Xbuf + row * 132 + seg * 4,
                   embB + (size_t)(lt + row) * DD + seg * 4,
                   (row < valid) ? 16 : 0);
    }
    #pragma unroll
    for (int j = 0; j < 4; ++j) {             // 1024 A float4-chunks
        int i = t + j * 256;
        int row = i >> 4, seg = i & 15;
        cp_async16(Abuf + row * RL + seg * 4,
                   Ac + (size_t)(lt + row) * RL + seg * 4, 16);
    }
}

__global__ __launch_bounds__(256) void k_stageA(
        const float* __restrict__ emb,
        const float* __restrict__ Bc,
        const float* __restrict__ Ac) {
    extern __shared__ float sm[];
    float* Bs  = sm;             // 2048
    float* Ys  = sm + 2048;      // 1280 (64 rows * stride 20)
    float* Xs  = sm + 3328;      // 8448 (64 rows * stride 132)
    float* As0 = sm + 11776;     // 4096
    float* As1 = sm + 15872;     // 4096

    int b     = blockIdx.x & (BB - 1);
    int chunk = blockIdx.x >> 6;
    int len   = g_len[b];
    int l0    = chunk * CHUNK;
    if (l0 >= len) return;
    int nrows = min(CHUNK, len - l0);
    int ntiles = (nrows + TILE - 1) >> 6;

    int t = threadIdx.x;
    const float* embB = emb + (size_t)b * LMAX * DD;

    // prologue: start tile-0 loads, then fill Bs
    issue_tile64(embB, Ac, Xs, As0, l0, min(TILE, nrows), t);
    cp_commit();
    #pragma unroll
    for (int j = 0; j < 2; ++j) {
        int i = t + j * 256;
        *(float4*)(Bs + i * 4) = *(const float4*)(Bc + i * 4);
    }

    // GEMM1 mapping
    int w    = t >> 5;
    int lane = t & 31;
    int cg   = w & 3;                 // column group: cols 4cg..4cg+3
    int row  = ((w >> 2) << 5) + lane;
    const float* xrow = Xs + row * 132;
    const float* bcol = Bs + cg * 4;
    float* yout = Ys + row * 20 + cg * 4;

    // GEMM2 mapping (accumulators persist)
    int k_own = t & 63;
    int rg    = t >> 6;               // 0..3
    float acc0 = 0.f, acc1 = 0.f, acc2 = 0.f, acc3 = 0.f;
    const float* yin = Ys + rg * 4;

    for (int tile = 0; tile < ntiles; ++tile) {
        const float* Ab = (tile & 1) ? As1 : As0;
        cp_wait<0>();
        __syncthreads();              // tile data ready; prev GEMM2 done

        // ---- GEMM1: y[row][4cg..] = sum_d X[row][d] * B[d][4cg..] ----
        float y0 = 0.f, y1 = 0.f, y2 = 0.f, y3 = 0.f;
        #pragma unroll 8
        for (int s = 0; s < 32; ++s) {
            float4 x4 = *(const float4*)(xrow + s * 4);
            float4 b0 = *(const float4*)(bcol + (4 * s + 0) * RD);
            float4 b1 = *(const float4*)(bcol + (4 * s + 1) * RD);
            float4 b2 = *(const float4*)(bcol + (4 * s + 2) * RD);
            float4 b3 = *(const float4*)(bcol + (4 * s + 3) * RD);
            y0 = fmaf(x4.x, b0.x, y0); y1 = fmaf(x4.x, b0.y, y1);
            y2 = fmaf(x4.x, b0.z, y2); y3 = fmaf(x4.x, b0.w, y3);
            y0 = fmaf(x4.y, b1.x, y0); y1 = fmaf(x4.y, b1.y, y1);
            y2 = fmaf(x4.y, b1.z, y2); y3 = fmaf(x4.y, b1.w, y3);
            y0 = fmaf(x4.z, b2.x, y0); y1 = fmaf(x4.z, b2.y, y1);
            y2 = fmaf(x4.z, b2.z, y2); y3 = fmaf(x4.z, b2.w, y3);
            y0 = fmaf(x4.w, b3.x, y0); y1 = fmaf(x4.w, b3.y, y1);
            y2 = fmaf(x4.w, b3.z, y2); y3 = fmaf(x4.w, b3.w, y3);
        }
        *(float4*)yout = make_float4(y0, y1, y2, y3);
        __syncthreads();              // Ys complete; X now dead

        // prefetch next tile (X into same buffer, A into alternate)
        if (tile + 1 < ntiles) {
            int lt    = l0 + (tile + 1) * TILE;
            int valid = min(TILE, nrows - (tile + 1) * TILE);
            issue_tile64(embB, Ac, Xs, (tile & 1) ? As0 : As1, lt, valid, t);
            cp_commit();
        }

        // ---- GEMM2: U[k][4rg..] += sum_l A[l][k] * y[l][4rg..] ----
        #pragma unroll 8
        for (int l = 0; l < TILE; ++l) {
            float a  = Ab[l * RL + k_own];
            float4 y = *(const float4*)(yin + l * 20);
            acc0 = fmaf(a, y.x, acc0);
            acc1 = fmaf(a, y.y, acc1);
            acc2 = fmaf(a, y.z, acc2);
            acc3 = fmaf(a, y.w, acc3);
        }
    }

    float* Ub = g_U + b * (RL * RD) + k_own * RD + rg * 4;
    atomicAdd(Ub + 0, acc0);
    atomicAdd(Ub + 1, acc1);
    atomicAdd(Ub + 2, acc2);
    atomicAdd(Ub + 3, acc3);
}

// -------------------------------------------------------------------
// Tail GEMM: C[64 x 512] += A[64 x Ktot] @ W[Ktot x 512] (+bias @ ks==0)
//   MODE 0: A=g_U  (Ktot=1024), C=g_z
//   MODE 1: A=g_z  (Ktot=512),  C=g_h
//   MODE 2: A=g_ha (Ktot=512),  C=outp, bias=b2
// KC=128: dynamic smem As[64*129] + Ws[128*32] = 49408 B.
// -------------------------------------------------------------------
template<int KC, int MODE>
__global__ __launch_bounds__(256) void k_tgemm(
        const float* __restrict__ W, float* __restrict__ outp,
        const float* __restrict__ bias, int Ktot) {
    const float* A = (MODE == 0) ? g_U : (MODE == 1) ? g_z : g_ha;
    float*       C = (MODE == 0) ? g_z : (MODE == 1) ? g_h : outp;

    constexpr int SA = KC + 1;
    extern __shared__ float tsm[];
    float* As = tsm;                 // BB * SA
    float* Ws = tsm + BB * SA;       // KC * 32

    int nt = blockIdx.x & 15;
    int ks = blockIdx.x >> 4;
    int n0 = nt * 32;
    int kbase = ks * KC;
    int t = threadIdx.x;

    #pragma unroll 4
    for (int i = t; i < BB * KC; i += 256) {
        int row = i / KC, k = i % KC;       // consecutive t -> consecutive k
        As[row * SA + k] = A[(size_t)row * Ktot + kbase + k];
    }
    #pragma unroll 4
    for (int i = t; i < KC * 8; i += 256) {
        int row = i >> 3, seg = i & 7;
        *(float4*)&Ws[row * 32 + seg * 4] =
            *(const float4*)&W[(size_t)(kbase + row) * DOUT + n0 + seg * 4];
    }
    __syncthreads();

    int l  = t & 31;
    int wn = t >> 5;          // 0..7 (warp-uniform -> Ws broadcast)
    float c00 = 0.f, c01 = 0.f, c02 = 0.f, c03 = 0.f;
    float c10 = 0.f, c11 = 0.f, c12 = 0.f, c13 = 0.f;
    const float* a0p = As + l * SA;
    const float* a1p = As + (l + 32) * SA;
    const float* wp  = Ws + wn * 4;
    #pragma unroll 8
    for (int k = 0; k < KC; ++k) {
        float a0 = a0p[k];
        float a1 = a1p[k];
        float4 w = *(const float4*)(wp + k * 32);
        c00 = fmaf(a0, w.x, c00); c01 = fmaf(a0, w.y, c01);
        c02 = fmaf(a0, w.z, c02); c03 = fmaf(a0, w.w, c03);
        c10 = fmaf(a1, w.x, c10); c11 = fmaf(a1, w.y, c11);
        c12 = fmaf(a1, w.z, c12); c13 = fmaf(a1, w.w, c13);
    }
    int col = n0 + wn * 4;
    if (MODE == 2 && ks == 0) {
        float4 bv = *(const float4*)(bias + col);
        c00 += bv.x; c01 += bv.y; c02 += bv.z; c03 += bv.w;
        c10 += bv.x; c11 += bv.y; c12 += bv.z; c13 += bv.w;
    }
    float* Cp0 = C + (size_t)l * DOUT + col;
    float* Cp1 = C + (size_t)(l + 32) * DOUT + col;
    atomicAdd(Cp0 + 0, c00); atomicAdd(Cp0 + 1, c01);
    atomicAdd(Cp0 + 2, c02); atomicAdd(Cp0 + 3, c03);
    atomicAdd(Cp1 + 0, c10); atomicAdd(Cp1 + 1, c11);
    atomicAdd(Cp1 + 2, c12); atomicAdd(Cp1 + 3, c13);
}

// -------------------------------------------------------------------
// k5: per-row bias + LayerNorm + ReLU. grid 64, 256 threads.
// -------------------------------------------------------------------
__global__ __launch_bounds__(256) void k_ln(const float* __restrict__ b1,
                                            const float* __restrict__ lnw,
                                            const float* __restrict__ lnb) {
    int b = blockIdx.x, t = threadIdx.x;
    float v0 = g_h[b * DOUT + t]       + b1[t];
    float v1 = g_h[b * DOUT + 256 + t] + b1[256 + t];
    float s  = v0 + v1;
    float sq = v0 * v0 + v1 * v1;
    for (int o = 16; o > 0; o >>= 1) {
        s  += __shfl_down_sync(0xFFFFFFFFu, s,  o);
        sq += __shfl_down_sync(0xFFFFFFFFu, sq, o);
    }
    __shared__ float rs[8], rq[8];
    if ((t & 31) == 0) { rs[t >> 5] = s; rq[t >> 5] = sq; }
    __syncthreads();
    float tot = 0.f, totq = 0.f;
    #pragma unroll
    for (int i = 0; i < 8; ++i) { tot += rs[i]; totq += rq[i]; }
    float mu  = tot / (float)DOUT;
    float var = fmaxf(totq / (float)DOUT - mu * mu, 0.f);
    float rstd = rsqrtf(var + LN_EPS);
    float o0 = (v0 - mu) * rstd * lnw[t]       + lnb[t];
    float o1 = (v1 - mu) * rstd * lnw[256 + t] + lnb[256 + t];
    g_ha[b * DOUT + t]       = fmaxf(o0, 0.f);
    g_ha[b * DOUT + 256 + t] = fmaxf(o1, 0.f);
}

// -------------------------------------------------------------------
extern "C" void kernel_launch(void* const* d_in, const int* in_sizes, int n_in,
                              void* d_out, int out_size) {
    const float*         emb  = (const float*)d_in[0];
    const unsigned char* mask = (const unsigned char*)d_in[1];
    const float*         Bc   = (const float*)d_in[2];
    const float*         Ac   = (const float*)d_in[3];
    const float*         Hc   = (const float*)d_in[4];
    const float*         W1   = (const float*)d_in[5];
    const float*         b1   = (const float*)d_in[6];
    const float*         lnw  = (const float*)d_in[7];
    const float*         lnb  = (const float*)d_in[8];
    const float*         W2   = (const float*)d_in[9];
    const float*         b2   = (const float*)d_in[10];
    float* out = (float*)d_out;

    const int TG_SMEM = (BB * 129 + 128 * 32) * 4;   // 49408 B

    cudaFuncSetAttribute(k_stageA, cudaFuncAttributeMaxDynamicSharedMemorySize, 81920);
    cudaFuncSetAttribute(k_tgemm<128, 0>, cudaFuncAttributeMaxDynamicSharedMemorySize, TG_SMEM);
    cudaFuncSetAttribute(k_tgemm<128, 1>, cudaFuncAttributeMaxDynamicSharedMemorySize, TG_SMEM);
    cudaFuncSetAttribute(k_tgemm<128, 2>, cudaFuncAttributeMaxDynamicSharedMemorySize, TG_SMEM);

    k_detect<<<1, 512>>>(mask);
    k_prep<<<68, 256>>>(mask, out);
    k_stageA<<<BB * (LMAX / CHUNK), 256, 79872>>>(emb, Bc, Ac);   // 512 blocks
    // z = U @ Hc   (K=1024, 8 K-splits -> 128 blocks)
    k_tgemm<128, 0><<<128, 256, TG_SMEM>>>(Hc, nullptr, nullptr, 1024);
    // h = z @ W1   (K=512, 4 K-splits -> 64 blocks)
    k_tgemm<128, 1><<<64, 256, TG_SMEM>>>(W1, nullptr, nullptr, 512);
    k_ln<<<BB, 256>>>(b1, lnw, lnb);
    // out = ha @ W2 + b2
    k_tgemm<128, 2><<<64, 256, TG_SMEM>>>(W2, out, b2, 512);
}